// round 15
// baseline (speedup 1.0000x reference)
#include <cuda_runtime.h>
#include <cuda_bf16.h>
#include <math.h>

// Problem constants
#define B 64
#define NA 33600            // 160*160 + 80*80 + 40*40
#define TOPK 500
#define CAND 1024           // candidate buffer size
#define NBIN 1024           // linear histogram bins over (0.3, 1.0]
#define SCORE_THRESH 0.3f
#define NMS_THRESH 0.5f
#define CLASS_OFFSET 10000.0f

#define P3_END 25600
#define P4_END 32000

typedef unsigned long long ull;

// ---------------- scratch (static device allocations; no runtime alloc) ----
struct ZeroBlock {               // zeroed by ONE memset node per launch
    int cnt[B];
    int hist[B][NBIN];
};
__device__ ZeroBlock g_zs;
__device__ float g_scores[B * NA];      // only the pathological fallback
__device__ ull   g_cand[B * NA];        // per-batch approx candidate keys

// ------------------------------------------------------------ exp/sigmoid --
// Correctly-rounded float exp via double exp (matches XLA:CPU expf).
// Verified bit-compatible in R4-R14 — DO NOT change.
__device__ __forceinline__ float exp_cr(float x) {
    return (float)exp((double)x);
}
__device__ __forceinline__ float sig_e(float x) {
    float e = exp_cr(-x);
    return __fdiv_rn(1.0f, __fadd_rn(1.0f, e));
}
// fast sigmoid for the approximate path (product abs err < ~3e-6)
__device__ __forceinline__ float sig_fast(float x) {
    return __fdividef(1.0f, 1.0f + __expf(-x));
}

__device__ __forceinline__ unsigned int ordered_float(float f) {
    unsigned int u = __float_as_uint(f);
    return (u & 0x80000000u) ? ~u : (u | 0x80000000u);
}
__device__ __forceinline__ float inv_ordered(unsigned int u) {
    return __uint_as_float((u & 0x80000000u) ? (u ^ 0x80000000u) : ~u);
}
__device__ __forceinline__ int bin_of(float s) {
    int q = (int)(__fmul_rn(__fsub_rn(s, 0.3f), 1462.857f));
    if (q < 0) q = 0;
    return (q > NBIN - 1) ? (NBIN - 1) : q;
}

__device__ __forceinline__ void level_of(int idx, int& HW, int& W, float& stride, int& p, int& lvl) {
    if (idx < P3_END)      { HW = 25600; W = 160; stride = 8.f;  p = idx;          lvl = 0; }
    else if (idx < P4_END) { HW = 6400;  W = 80;  stride = 16.f; p = idx - P3_END; lvl = 1; }
    else                   { HW = 1600;  W = 40;  stride = 32.f; p = idx - P4_END; lvl = 2; }
}

// =================== kernel 1: highly-parallel approx scan =================
__global__ __launch_bounds__(512)
void scan_kernel(const float* __restrict__ cls3,
                 const float* __restrict__ obj3,
                 const float* __restrict__ cls4,
                 const float* __restrict__ obj4,
                 const float* __restrict__ cls5,
                 const float* __restrict__ obj5)
{
    __shared__ int   s_idx[2048];
    __shared__ float s_ap[2048];
    __shared__ int   s_hist[NBIN];
    __shared__ int   s_n, s_base;

    int b   = blockIdx.y;
    int tid = threadIdx.x;

    for (int d = tid; d < NBIN; d += 512) s_hist[d] = 0;
    if (tid == 0) s_n = 0;
    __syncthreads();

    int t = blockIdx.x * 512 + tid;
    int a = t * 4;
    if (a < NA) {
        const float* cls; const float* obj; int HW, p;
        if (a < P3_END)      { cls = cls3; obj = obj3; HW = 25600; p = a; }
        else if (a < P4_END) { cls = cls4; obj = obj4; HW = 6400;  p = a - P3_END; }
        else                 { cls = cls5; obj = obj5; HW = 1600;  p = a - P4_END; }

        float4 o4  = *(const float4*)(obj + b * HW + p);
        float4 c04 = *(const float4*)(cls + (b * 2 + 0) * HW + p);
        float4 c14 = *(const float4*)(cls + (b * 2 + 1) * HW + p);
        float oo[4]  = {o4.x, o4.y, o4.z, o4.w};
        float cc0[4] = {c04.x, c04.y, c04.z, c04.w};
        float cc1[4] = {c14.x, c14.y, c14.z, c14.w};

        #pragma unroll
        for (int j = 0; j < 4; ++j) {
            float cm = fmaxf(cc0[j], cc1[j]);
            float v  = sig_fast(oo[j]) * sig_fast(cm);
            if (v >= 0.29999f) {
                int pos = atomicAdd(&s_n, 1);
                s_idx[pos] = a + j; s_ap[pos] = v;
                atomicAdd(&s_hist[bin_of(v)], 1);
            }
        }
    }
    __syncthreads();

    if (tid == 0 && s_n) s_base = atomicAdd(&g_zs.cnt[b], s_n);
    __syncthreads();

    int n = s_n;
    for (int i = tid; i < n; i += 512) {
        g_cand[b * NA + s_base + i] =
            ((ull)ordered_float(s_ap[i]) << 32) |
            (unsigned int)(~(unsigned int)s_idx[i]);
    }
    for (int d = tid; d < NBIN; d += 512) {
        int h = s_hist[d];
        if (h) atomicAdd(&g_zs.hist[b][d], h);
    }
}

// ========== kernel 2: select (exact top-k) + adjacency + greedy + out ======
__global__ __launch_bounds__(1024, 1)
void select_nms_kernel(const float* __restrict__ cls3,
                       const float* __restrict__ reg3,
                       const float* __restrict__ obj3,
                       const float* __restrict__ cls4,
                       const float* __restrict__ reg4,
                       const float* __restrict__ obj4,
                       const float* __restrict__ cls5,
                       const float* __restrict__ reg5,
                       const float* __restrict__ obj5,
                       float* __restrict__ out)
{
    // shared union:
    //  select phase: hist[0,4K) cidx[4K,8K) ukey[8K,16K) sorted[16K,24K)
    //  NMS phase:    sbox[0,8K) sar[8K,10K) adj[10240,43008)
    __shared__ __align__(16) unsigned char smem_raw[43008];
    int*    hist = (int*)smem_raw;
    int*    cidx = (int*)(smem_raw + 4096);
    ull*    ukey = (ull*)(smem_raw + 8192);
    ull*    skey = (ull*)(smem_raw + 16384);
    float4* sbox = (float4*)smem_raw;
    float*  sar  = (float*)(smem_raw + 8192);
    unsigned int* adj = (unsigned int*)(smem_raw + 10240);

    __shared__ int  coarse[NBIN / 4];
    __shared__ int  s_qp, s_cnt, s_nvalid, s_fallback;
    __shared__ ull  s_prefix;
    __shared__ int  s_k;
    __shared__ unsigned int s_validw[16];
    __shared__ unsigned int skeepw[16];
    __shared__ unsigned int s_vbm[32];
    __shared__ int  s_wpre[33];

    int b   = blockIdx.x;
    int tid = threadIdx.x;
    const int NT = 1024;
    int cnt_all = g_zs.cnt[b];

    const float* CLS[3] = {cls3, cls4, cls5};
    const float* REG[3] = {reg3, reg4, reg5};
    const float* OBJ[3] = {obj3, obj4, obj5};

    if (tid == 0) { s_cnt = 0; s_nvalid = 0; s_fallback = 0; }
    if (tid < 32) s_vbm[tid] = 0u;
    __syncthreads();

    const ull* cl = g_cand + b * NA;

    if (cnt_all <= CAND) {
        for (int i = tid; i < cnt_all; i += NT)
            cidx[i] = (int)(~(unsigned int)cl[i]);
        if (tid == 0) s_cnt = cnt_all;
        __syncthreads();
    } else {
        for (int d = tid; d < NBIN; d += NT) hist[d] = g_zs.hist[b][d];
        __syncthreads();
        if (tid < NBIN / 4)
            coarse[tid] = hist[4 * tid] + hist[4 * tid + 1] + hist[4 * tid + 2] + hist[4 * tid + 3];
        __syncthreads();
        if (tid == 0) {
            int cum = 0, qp = 0;
            for (int g = NBIN / 4 - 1; g >= 0; --g) {
                if (cum + coarse[g] >= TOPK) {
                    for (int d = 4 * g + 3; d >= 4 * g; --d) {
                        if (cum + hist[d] >= TOPK) { qp = d; break; }
                        cum += hist[d];
                    }
                    break;
                }
                cum += coarse[g];
            }
            s_qp = (qp > 0) ? qp - 1 : 0;
        }
        __syncthreads();
        int qp = s_qp;
        for (int i = tid; i < cnt_all; i += NT) {
            ull key = cl[i];
            float s = inv_ordered((unsigned int)(key >> 32));
            if (bin_of(s) >= qp) {
                int pos = atomicAdd(&s_cnt, 1);
                if (pos < CAND) cidx[pos] = (int)(~(unsigned int)key);
                else            s_fallback = 1;
            }
        }
        __syncthreads();
    }

    if (!s_fallback) {
        int m = s_cnt; if (m > CAND) m = CAND;
        for (int it = tid; it < m; it += NT) {
            int idx = cidx[it];
            int HW, W, p, lvl; float stride;
            level_of(idx, HW, W, stride, p, lvl);
            const float* cls = CLS[lvl];
            const float* obj = OBJ[lvl];
            float o  = obj[b * HW + p];
            float c0 = cls[(b * 2 + 0) * HW + p];
            float c1 = cls[(b * 2 + 1) * HW + p];
            float cmax = fmaxf(c0, c1);
            float smax = __fmul_rn(sig_e(o), sig_e(cmax));  // == max(s0,s1)
            ull key = 0ull;
            if (smax > SCORE_THRESH) {
                key = ((ull)ordered_float(smax) << 32) |
                      (unsigned int)(~(unsigned int)idx);
                atomicAdd(&s_nvalid, 1);
                if ((unsigned int)idx < 1024u)
                    atomicOr(&s_vbm[idx >> 5], 1u << (idx & 31));
            }
            ukey[it] = key;
        }
        __syncthreads();

        if (s_nvalid < TOPK) {
            int M = TOPK - s_nvalid;
            if (cnt_all <= CAND && s_cnt + M <= CAND) {
                if (tid == 0) {
                    int acc = 0;
                    for (int w = 0; w < 32; ++w) {
                        s_wpre[w] = acc;
                        acc += 32 - __popc(s_vbm[w]);
                    }
                    s_wpre[32] = acc;
                }
                __syncthreads();
                int base2 = s_cnt;
                {
                    int i = tid;   // NT == 1024 covers [0,1024)
                    unsigned int bmw = s_vbm[i >> 5];
                    bool invalid = !((bmw >> (i & 31)) & 1u);
                    if (invalid) {
                        int rank = s_wpre[i >> 5] +
                                   __popc(~bmw & ((1u << (i & 31)) - 1u));
                        if (rank < M) {
                            ukey[base2 + rank] =
                                ((ull)ordered_float(-1.0f) << 32) |
                                (unsigned int)(~(unsigned int)i);
                        }
                    }
                }
                __syncthreads();
                if (tid == 0) s_cnt = base2 + M;
                __syncthreads();
            } else {
                s_fallback = 1;
            }
        }
    }
    __syncthreads();

    // pathological full-exact fallback (correct, slow, unexpected)
    if (s_fallback) {
        float* sc = g_scores + b * NA;
        for (int i = tid; i < NA; i += NT) {
            int HW, W, p, lvl; float stride;
            level_of(i, HW, W, stride, p, lvl);
            const float* cls = CLS[lvl];
            const float* obj = OBJ[lvl];
            float o  = obj[b * HW + p];
            float c0 = cls[(b * 2 + 0) * HW + p];
            float c1 = cls[(b * 2 + 1) * HW + p];
            float smax = __fmul_rn(sig_e(o), sig_e(fmaxf(c0, c1)));
            sc[i] = (smax > SCORE_THRESH) ? smax : -1.0f;
        }
        if (tid == 0) { s_prefix = 0ull; s_k = TOPK; s_cnt = 0; }
        __syncthreads();
        for (int pp = 7; pp >= 0; --pp) {
            for (int d = tid; d < 256; d += NT) hist[d] = 0;
            __syncthreads();
            ull pref = s_prefix;
            int sh = (pp + 1) * 8;
            for (int i = tid; i < NA; i += NT) {
                ull key = ((ull)ordered_float(sc[i]) << 32) |
                          (unsigned int)(~(unsigned int)i);
                bool match = (pp == 7) || ((key >> sh) == (pref >> sh));
                if (match) atomicAdd(&hist[(unsigned int)(key >> (pp * 8)) & 0xFFu], 1);
            }
            __syncthreads();
            if (tid == 0) {
                int k = s_k;
                for (int d = 255; d >= 0; --d) {
                    int c = hist[d];
                    if (k <= c) { s_prefix = pref | ((ull)d << (pp * 8)); break; }
                    k -= c;
                }
                s_k = k;
            }
            __syncthreads();
        }
        ull pivot = s_prefix;
        for (int i = tid; i < NA; i += NT) {
            ull key = ((ull)ordered_float(sc[i]) << 32) |
                      (unsigned int)(~(unsigned int)i);
            if (key >= pivot) {
                int pos = atomicAdd(&s_cnt, 1);
                if (pos < CAND) ukey[pos] = key;
            }
        }
        __syncthreads();
    }

    // ---- rank-by-enumeration sort (replaces 55-stage bitonic) ------------
    // keys unique (score||~idx); rank = #{keys > mine} gives the exact
    // descending position. zero keys (invalid) stay in the zero-initialized
    // tail — identical to bitonic's output.
    int cnt = s_cnt; if (cnt > CAND) cnt = CAND;
    skey[tid] = 0ull;
    __syncthreads();
    {
        ull mykey = (tid < cnt) ? ukey[tid] : 0ull;
        if (mykey != 0ull) {
            int rank = 0;
            #pragma unroll 8
            for (int j = 0; j < cnt; ++j)
                rank += (ukey[j] > mykey) ? 1 : 0;   // LDS broadcast per j
            if (rank < CAND) skey[rank] = mykey;
        }
    }
    __syncthreads();

    // ---- transition: grab my key, repurpose shared for NMS ----
    ull myk = skey[tid];
    __syncthreads();

    // ---- box + label decode for top-500 ----
    int r = tid;
    float4 bb = make_float4(0.f, 0.f, 0.f, 0.f);
    float  sc = -1.0f;
    int    lab = 0;
    bool   validf = false;

    if (r < TOPK) {
        int idx = (int)(~(unsigned int)myk);
        sc = inv_ordered((unsigned int)(myk >> 32));
        if ((unsigned int)idx >= (unsigned int)NA) idx = 0;   // defensive

        int HW, W, p, lvl; float stride;
        level_of(idx, HW, W, stride, p, lvl);
        const float* reg = REG[lvl];
        const float* cls = CLS[lvl];
        const float* obj = OBJ[lvl];
        int y = p / W;
        int x = p - y * W;

        float dx = reg[(b * 4 + 0) * HW + p];
        float dy = reg[(b * 4 + 1) * HW + p];
        float dw = reg[(b * 4 + 2) * HW + p];
        float dh = reg[(b * 4 + 3) * HW + p];
        float cx = __fmul_rn(__fadd_rn((float)x, sig_e(dx)), stride);
        float cy = __fmul_rn(__fadd_rn((float)y, sig_e(dy)), stride);
        float w  = __fmul_rn(exp_cr(dw), stride);
        float h  = __fmul_rn(exp_cr(dh), stride);
        float wh = __fdiv_rn(w, 2.0f);
        float hh = __fdiv_rn(h, 2.0f);
        bb.x = __fsub_rn(cx, wh);
        bb.y = __fsub_rn(cy, hh);
        bb.z = __fadd_rn(cx, wh);
        bb.w = __fadd_rn(cy, hh);

        float c0 = cls[(b * 2 + 0) * HW + p];
        float c1 = cls[(b * 2 + 1) * HW + p];
        if (c1 > c0) {
            if (__fsub_rn(c1, c0) < 1e-3f) {
                float o   = obj[b * HW + p];
                float so2 = sig_e(o);
                float s0  = __fmul_rn(so2, sig_e(c0));
                float s1  = __fmul_rn(so2, sig_e(c1));
                lab = (s1 > s0) ? 1 : 0;
            } else {
                lab = 1;
            }
        }

        float off = __fmul_rn((float)lab, CLASS_OFFSET);
        float x1 = __fadd_rn(bb.x, off);
        float y1 = __fadd_rn(bb.y, off);
        float x2 = __fadd_rn(bb.z, off);
        float y2 = __fadd_rn(bb.w, off);
        sbox[r] = make_float4(x1, y1, x2, y2);
        sar[r]  = __fmul_rn(__fsub_rn(x2, x1), __fsub_rn(y2, y1));
        validf  = (sc > SCORE_THRESH);
    } else if (r < 512) {
        sbox[r] = make_float4(0.f, 0.f, 0.f, 0.f);
        sar[r]  = 0.f;
    }

    unsigned vb = __ballot_sync(0xFFFFFFFFu, validf);
    if (r < 512 && (r & 31) == 0) s_validw[r >> 5] = vb;

    #pragma unroll
    for (int w = 0; w < 8; ++w) adj[tid * 8 + w] = 0u;   // 512*16 words / 1024 thr
    __syncthreads();

    // ---- adjacency: balanced half-pair enumeration, 2 threads per row ----
    {
        int row = tid >> 1;
        int h   = tid & 1;
        float4 mb = sbox[row];
        float  ar = sar[row];
        int kmax = (row < 256) ? 256 : 255;
        int k0 = h ? 129 : 1;
        int k1 = h ? kmax : 128;
        for (int k = k0; k <= k1; ++k) {
            int j = (row + k) & 511;
            float4 bj = sbox[j];
            float  aj = sar[j];
            float ix1 = fmaxf(mb.x, bj.x);
            float iy1 = fmaxf(mb.y, bj.y);
            float ix2 = fminf(mb.z, bj.z);
            float iy2 = fminf(mb.w, bj.w);
            float iw  = fmaxf(__fsub_rn(ix2, ix1), 0.f);
            float ih  = fmaxf(__fsub_rn(iy2, iy1), 0.f);
            float inter = __fmul_rn(iw, ih);
            float uniP  = __fadd_rn(__fsub_rn(__fadd_rn(ar, aj), inter), 1e-7f);
            float t2   = __fmul_rn(0.5f, uniP);
            float diff = __fsub_rn(inter, t2);
            bool hit;
            if (fabsf(diff) <= __fmul_rn(1e-6f, t2)) {
                float iou = __fdiv_rn(inter, uniP);   // exact decision in band
                hit = (iou >= NMS_THRESH);
            } else {
                hit = (diff > 0.f);
            }
            if (hit) {
                atomicOr(&adj[row * 16 + (j >> 5)], 1u << (j & 31));
                atomicOr(&adj[j * 16 + (row >> 5)], 1u << (row & 31));
            }
        }
    }
    __syncthreads();

    // ---- windowed warp greedy (R13): 16 shfls, local window resolution ----
    if (tid < 32) {
        int lane = tid;
        unsigned avail = (lane < 16) ? s_validw[lane] : 0u;
        #pragma unroll 1
        for (int w = 0; w < 16; ++w) {
            unsigned km = 0;
            if (lane == w) {
                unsigned aw = avail;
                unsigned col[32];
                #pragma unroll
                for (int b2 = 0; b2 < 32; ++b2)
                    col[b2] = adj[(w * 32 + b2) * 16 + w];
                #pragma unroll
                for (int b2 = 0; b2 < 32; ++b2) {
                    if ((aw >> b2) & 1u) {
                        km |= 1u << b2;
                        aw &= ~col[b2];
                    }
                }
            }
            km = __shfl_sync(0xFFFFFFFFu, km, w);
            if (lane < 16) {
                #pragma unroll
                for (int b2 = 0; b2 < 32; ++b2) {
                    if ((km >> b2) & 1u)
                        avail &= ~adj[(w * 32 + b2) * 16 + lane];
                }
            }
            if (lane == 0) skeepw[w] = km;
        }
    }
    __syncthreads();

    // ---- outputs: [boxes (B*500*4)] [scores] [labels] [keep] ----
    if (r < TOPK) {
        bool kp = (skeepw[r >> 5] >> (r & 31)) & 1u;
        int row = b * TOPK + r;
        float* ob = out + row * 4;
        ob[0] = kp ? bb.x : 0.f;
        ob[1] = kp ? bb.y : 0.f;
        ob[2] = kp ? bb.z : 0.f;
        ob[3] = kp ? bb.w : 0.f;
        const int SBASE = B * TOPK * 4;
        const int LBASE = SBASE + B * TOPK;
        const int KBASE = LBASE + B * TOPK;
        out[SBASE + row] = kp ? sc : 0.f;
        out[LBASE + row] = (float)lab;
        out[KBASE + row] = kp ? 1.f : 0.f;
    }
}

// --------------------------------------------------------------- launch ----
extern "C" void kernel_launch(void* const* d_in, const int* in_sizes, int n_in,
                              void* d_out, int out_size)
{
    const float* cls_p3 = (const float*)d_in[0];
    const float* reg_p3 = (const float*)d_in[1];
    const float* obj_p3 = (const float*)d_in[2];
    const float* cls_p4 = (const float*)d_in[3];
    const float* reg_p4 = (const float*)d_in[4];
    const float* obj_p4 = (const float*)d_in[5];
    const float* cls_p5 = (const float*)d_in[6];
    const float* reg_p5 = (const float*)d_in[7];
    const float* obj_p5 = (const float*)d_in[8];
    float* out = (float*)d_out;

    void* p_zs = nullptr;
    cudaGetSymbolAddress(&p_zs, g_zs);
    cudaMemsetAsync(p_zs, 0, sizeof(ZeroBlock), 0);   // ONE memset node

    dim3 sgrid(17, B);
    scan_kernel<<<sgrid, 512>>>(cls_p3, obj_p3, cls_p4, obj_p4, cls_p5, obj_p5);
    select_nms_kernel<<<B, 1024>>>(cls_p3, reg_p3, obj_p3,
                                   cls_p4, reg_p4, obj_p4,
                                   cls_p5, reg_p5, obj_p5, out);
}